// round 2
// baseline (speedup 1.0000x reference)
#include <cuda_runtime.h>
#include <cuda_bf16.h>

#define N_NODES 50000
#define N_EDGES 800000
#define DIM 128
#define NCLS 16

// ---------------- scratch (allocation-free: __device__ globals) ----------------
__device__ float g_h[N_NODES * DIM];      // post-GEMM features
__device__ float g_x[N_NODES * DIM];      // current layer activations
__device__ float g_res[N_NODES * DIM];    // residual branch
__device__ float g_iso[N_NODES];
__device__ float g_isi[N_NODES];
__device__ int   g_dego[N_NODES];
__device__ int   g_degi[N_NODES];
__device__ int   g_rowptr[N_NODES + 1];
__device__ int   g_cursor[N_NODES];
__device__ int   g_esrc[N_EDGES];
__device__ float g_eww[N_EDGES];

// ---------------- kernels ----------------
__global__ void k_zero_deg() {
    int i = blockIdx.x * blockDim.x + threadIdx.x;
    if (i < N_NODES) { g_dego[i] = 0; g_degi[i] = 0; }
}

__global__ void k_degrees(const int* __restrict__ src, const int* __restrict__ dst) {
    int e = blockIdx.x * blockDim.x + threadIdx.x;
    if (e < N_EDGES) {
        atomicAdd(&g_dego[src[e]], 1);
        atomicAdd(&g_degi[dst[e]], 1);
    }
}

__global__ void k_invsqrt() {
    int i = blockIdx.x * blockDim.x + threadIdx.x;
    if (i < N_NODES) {
        int dout = g_dego[i]; if (dout < 1) dout = 1;
        int din  = g_degi[i]; if (din  < 1) din  = 1;
        g_iso[i] = rsqrtf((float)dout);
        g_isi[i] = rsqrtf((float)din);
    }
}

// single-block exclusive scan over g_degi -> g_rowptr (+ cursor copy)
__global__ void k_scan() {
    __shared__ int wsum[32];
    __shared__ int carry_s;
    int t = threadIdx.x, lane = t & 31, w = t >> 5;
    if (t == 0) carry_s = 0;
    __syncthreads();
    for (int base = 0; base < N_NODES; base += 1024) {
        int i = base + t;
        int v = (i < N_NODES) ? g_degi[i] : 0;
        int x = v;
        #pragma unroll
        for (int off = 1; off < 32; off <<= 1) {
            int y = __shfl_up_sync(0xffffffffu, x, off);
            if (lane >= off) x += y;
        }
        if (lane == 31) wsum[w] = x;
        __syncthreads();
        if (w == 0) {
            int s = wsum[lane];
            int xs = s;
            #pragma unroll
            for (int off = 1; off < 32; off <<= 1) {
                int y = __shfl_up_sync(0xffffffffu, xs, off);
                if (lane >= off) xs += y;
            }
            wsum[lane] = xs - s;  // exclusive warp offsets
        }
        __syncthreads();
        int carry = carry_s;
        int excl = carry + wsum[w] + (x - v);
        if (i < N_NODES) { g_rowptr[i] = excl; g_cursor[i] = excl; }
        __syncthreads();
        if (t == 1023) carry_s = excl + v;
        __syncthreads();
    }
    if (t == 0) g_rowptr[N_NODES] = carry_s;
}

__global__ void k_fill_csr(const int* __restrict__ src, const int* __restrict__ dst,
                           const float* __restrict__ ew) {
    int e = blockIdx.x * blockDim.x + threadIdx.x;
    if (e < N_EDGES) {
        int d = dst[e];
        int p = atomicAdd(&g_cursor[d], 1);
        g_esrc[p] = src[e];
        g_eww[p]  = ew[e];
    }
}

// C[N,128] = (A (*) scale) @ W (+ bias). W row-major [128,128].
#define GBM 64
#define GBK 32
__global__ void __launch_bounds__(256) k_gemm128(
    const float* __restrict__ A, const float* __restrict__ scale,
    const float* __restrict__ W, const float* __restrict__ bias,
    float* __restrict__ C) {
    __shared__ float As[GBM][GBK + 4];   // stride 36, float4-aligned
    __shared__ float Ws[GBK][DIM];
    const int tid  = threadIdx.x;
    const int row0 = blockIdx.x * GBM;
    const int lrow = tid >> 2;           // 0..63
    const int lq   = tid & 3;            // quad
    const int grow = row0 + lrow;
    const float s  = (grow < N_NODES) ? (scale ? scale[grow] : 1.0f) : 0.0f;
    const int tcol = tid & 31;           // 0..31
    const int trow = tid >> 5;           // 0..7
    float acc[8][4];
    #pragma unroll
    for (int m = 0; m < 8; m++)
        #pragma unroll
        for (int n = 0; n < 4; n++) acc[m][n] = 0.0f;

    for (int k0 = 0; k0 < DIM; k0 += GBK) {
        // A tile: 64 x 32, scaled
        if (grow < N_NODES) {
            float4 v0 = *(const float4*)&A[grow * DIM + k0 + lq * 4];
            float4 v1 = *(const float4*)&A[grow * DIM + k0 + (lq + 4) * 4];
            v0.x *= s; v0.y *= s; v0.z *= s; v0.w *= s;
            v1.x *= s; v1.y *= s; v1.z *= s; v1.w *= s;
            *(float4*)&As[lrow][lq * 4]       = v0;
            *(float4*)&As[lrow][(lq + 4) * 4] = v1;
        } else {
            float4 z = make_float4(0.f, 0.f, 0.f, 0.f);
            *(float4*)&As[lrow][lq * 4]       = z;
            *(float4*)&As[lrow][(lq + 4) * 4] = z;
        }
        // W tile: 32 x 128
        #pragma unroll
        for (int i = 0; i < 4; i++) {
            int u = tid + 256 * i;          // 0..1023 float4 units
            int wr = u >> 5, wc = (u & 31) * 4;
            *(float4*)&Ws[wr][wc] = *(const float4*)&W[(k0 + wr) * DIM + wc];
        }
        __syncthreads();
        #pragma unroll
        for (int k = 0; k < GBK; k++) {
            float4 b = *(const float4*)&Ws[k][tcol * 4];
            #pragma unroll
            for (int m = 0; m < 8; m++) {
                float a = As[trow * 8 + m][k];
                acc[m][0] += a * b.x;
                acc[m][1] += a * b.y;
                acc[m][2] += a * b.z;
                acc[m][3] += a * b.w;
            }
        }
        __syncthreads();
    }
    float4 bb = make_float4(0.f, 0.f, 0.f, 0.f);
    if (bias) bb = *(const float4*)&bias[tcol * 4];
    #pragma unroll
    for (int m = 0; m < 8; m++) {
        int gr = row0 + trow * 8 + m;
        if (gr < N_NODES) {
            float4 o;
            o.x = acc[m][0] + bb.x; o.y = acc[m][1] + bb.y;
            o.z = acc[m][2] + bb.z; o.w = acc[m][3] + bb.w;
            *(float4*)&C[gr * DIM + tcol * 4] = o;
        }
    }
}

// one warp per destination row: acc = sum_e w_e * h[src_e]; out = f(acc*isi + b [+res])
__global__ void __launch_bounds__(256) k_spmm(
    const float* __restrict__ h, const float* __restrict__ bias,
    const float* __restrict__ res, float* __restrict__ out, int do_relu) {
    int warp = (blockIdx.x * blockDim.x + threadIdx.x) >> 5;
    int lane = threadIdx.x & 31;
    if (warp >= N_NODES) return;
    int beg = g_rowptr[warp], end = g_rowptr[warp + 1];
    float4 acc = make_float4(0.f, 0.f, 0.f, 0.f);
    int e = beg;
    for (; e + 1 < end; e += 2) {
        int   s0 = g_esrc[e],   s1 = g_esrc[e + 1];
        float w0 = g_eww[e],    w1 = g_eww[e + 1];
        float4 v0 = *(const float4*)&h[s0 * DIM + lane * 4];
        float4 v1 = *(const float4*)&h[s1 * DIM + lane * 4];
        acc.x += w0 * v0.x + w1 * v1.x;
        acc.y += w0 * v0.y + w1 * v1.y;
        acc.z += w0 * v0.z + w1 * v1.z;
        acc.w += w0 * v0.w + w1 * v1.w;
    }
    if (e < end) {
        int s0 = g_esrc[e]; float w0 = g_eww[e];
        float4 v0 = *(const float4*)&h[s0 * DIM + lane * 4];
        acc.x += w0 * v0.x; acc.y += w0 * v0.y;
        acc.z += w0 * v0.z; acc.w += w0 * v0.w;
    }
    float si = g_isi[warp];
    float4 b = *(const float4*)&bias[lane * 4];
    float4 o;
    o.x = acc.x * si + b.x; o.y = acc.y * si + b.y;
    o.z = acc.z * si + b.z; o.w = acc.w * si + b.w;
    if (res) {
        float4 r = *(const float4*)&res[warp * DIM + lane * 4];
        o.x += r.x; o.y += r.y; o.z += r.z; o.w += r.w;
    }
    if (do_relu) {
        o.x = fmaxf(o.x, 0.f); o.y = fmaxf(o.y, 0.f);
        o.z = fmaxf(o.z, 0.f); o.w = fmaxf(o.w, 0.f);
    }
    *(float4*)&out[warp * DIM + lane * 4] = o;
}

// out[N,16] = z[N,128] @ Wo[128,16] + bo
__global__ void __launch_bounds__(256) k_out(
    const float* __restrict__ z, const float* __restrict__ Wo,
    const float* __restrict__ bo, float* __restrict__ out) {
    __shared__ float sz[64][132];
    __shared__ float sw[DIM][NCLS];
    int r0 = blockIdx.x * 64;
    for (int i = threadIdx.x; i < DIM * NCLS; i += 256)
        sw[i >> 4][i & 15] = Wo[i];
    for (int i = threadIdx.x; i < 2048; i += 256) {   // 64 rows x 32 float4
        int row = i >> 5, c4 = (i & 31) * 4;
        int gr = r0 + row;
        float4 v = (gr < N_NODES) ? *(const float4*)&z[gr * DIM + c4]
                                  : make_float4(0.f, 0.f, 0.f, 0.f);
        *(float4*)&sz[row][c4] = v;
    }
    __syncthreads();
    int row = threadIdx.x >> 2;
    int cg  = (threadIdx.x & 3) * 4;
    float a0 = 0.f, a1 = 0.f, a2 = 0.f, a3 = 0.f;
    #pragma unroll 8
    for (int k = 0; k < DIM; k++) {
        float zv = sz[row][k];
        a0 += zv * sw[k][cg];     a1 += zv * sw[k][cg + 1];
        a2 += zv * sw[k][cg + 2]; a3 += zv * sw[k][cg + 3];
    }
    int gr = r0 + row;
    if (gr < N_NODES) {
        out[gr * NCLS + cg]     = a0 + bo[cg];
        out[gr * NCLS + cg + 1] = a1 + bo[cg + 1];
        out[gr * NCLS + cg + 2] = a2 + bo[cg + 2];
        out[gr * NCLS + cg + 3] = a3 + bo[cg + 3];
    }
}

// ---------------- launch ----------------
extern "C" void kernel_launch(void* const* d_in, const int* in_sizes, int n_in,
                              void* d_out, int out_size) {
    const int*   src = (const int*)d_in[0];
    const int*   dst = (const int*)d_in[1];
    const float* xin = (const float*)d_in[2];
    const float* ew  = (const float*)d_in[3];
    const float* W1 = (const float*)d_in[4];  const float* b1 = (const float*)d_in[5];
    const float* W2 = (const float*)d_in[6];  const float* b2 = (const float*)d_in[7];
    const float* W3 = (const float*)d_in[8];  const float* b3 = (const float*)d_in[9];
    const float* W4 = (const float*)d_in[10]; const float* b4 = (const float*)d_in[11];
    const float* Wr = (const float*)d_in[12]; const float* br = (const float*)d_in[13];
    const float* Wo = (const float*)d_in[14]; const float* bo = (const float*)d_in[15];
    float* out = (float*)d_out;

    float *p_h, *p_x, *p_res, *p_iso;
    cudaGetSymbolAddress((void**)&p_h,   g_h);
    cudaGetSymbolAddress((void**)&p_x,   g_x);
    cudaGetSymbolAddress((void**)&p_res, g_res);
    cudaGetSymbolAddress((void**)&p_iso, g_iso);

    const int TB = 256;
    int nB_nodes = (N_NODES + TB - 1) / TB;       // 196
    int nB_edges = (N_EDGES + TB - 1) / TB;       // 3125
    int nB_gemm  = (N_NODES + GBM - 1) / GBM;     // 782
    int nB_spmm  = (N_NODES + (TB / 32) - 1) / (TB / 32);  // 6250

    // graph preprocessing (identical for all 4 layers)
    k_zero_deg<<<nB_nodes, TB>>>();
    k_degrees<<<nB_edges, TB>>>(src, dst);
    k_invsqrt<<<nB_nodes, TB>>>();
    k_scan<<<1, 1024>>>();
    k_fill_csr<<<nB_edges, TB>>>(src, dst, ew);

    // residual branch
    k_gemm128<<<nB_gemm, TB>>>(xin, nullptr, Wr, br, p_res);

    // layer 1
    k_gemm128<<<nB_gemm, TB>>>(xin, p_iso, W1, nullptr, p_h);
    k_spmm<<<nB_spmm, TB>>>(p_h, b1, nullptr, p_x, 1);
    // layer 2
    k_gemm128<<<nB_gemm, TB>>>(p_x, p_iso, W2, nullptr, p_h);
    k_spmm<<<nB_spmm, TB>>>(p_h, b2, nullptr, p_x, 1);
    // layer 3
    k_gemm128<<<nB_gemm, TB>>>(p_x, p_iso, W3, nullptr, p_h);
    k_spmm<<<nB_spmm, TB>>>(p_h, b3, nullptr, p_x, 1);
    // layer 4 + residual + relu
    k_gemm128<<<nB_gemm, TB>>>(p_x, p_iso, W4, nullptr, p_h);
    k_spmm<<<nB_spmm, TB>>>(p_h, b4, p_res, p_x, 1);

    // output head
    k_out<<<nB_gemm, TB>>>(p_x, Wo, bo, out);
}

// round 3
// speedup vs baseline: 1.0013x; 1.0013x over previous
#include <cuda_runtime.h>
#include <cuda_bf16.h>

#define N_NODES 50000
#define N_EDGES 800000
#define DIM 128
#define NCLS 16

// ---------------- scratch (allocation-free: __device__ globals) ----------------
__device__ float g_h[N_NODES * DIM];      // post-GEMM features
__device__ float g_x[N_NODES * DIM];      // current layer activations
__device__ float g_res[N_NODES * DIM];    // residual branch
__device__ float g_iso[N_NODES];
__device__ float g_isi[N_NODES];
__device__ int   g_dego[N_NODES];
__device__ int   g_degi[N_NODES];
__device__ int   g_rowptr[N_NODES + 1];
__device__ int   g_cursor[N_NODES];
__device__ int   g_esrc[N_EDGES];
__device__ float g_eww[N_EDGES];

// ---------------- kernels ----------------
__global__ void k_zero_deg() {
    int i = blockIdx.x * blockDim.x + threadIdx.x;
    if (i < N_NODES) { g_dego[i] = 0; g_degi[i] = 0; }
}

__global__ void k_degrees(const int* __restrict__ src, const int* __restrict__ dst) {
    int e = blockIdx.x * blockDim.x + threadIdx.x;
    if (e < N_EDGES) {
        atomicAdd(&g_dego[src[e]], 1);
        atomicAdd(&g_degi[dst[e]], 1);
    }
}

__global__ void k_invsqrt() {
    int i = blockIdx.x * blockDim.x + threadIdx.x;
    if (i < N_NODES) {
        int dout = g_dego[i]; if (dout < 1) dout = 1;
        int din  = g_degi[i]; if (din  < 1) din  = 1;
        g_iso[i] = rsqrtf((float)dout);
        g_isi[i] = rsqrtf((float)din);
    }
}

// single-block exclusive scan over g_degi -> g_rowptr (+ cursor copy)
__global__ void k_scan() {
    __shared__ int wsum[32];
    __shared__ int carry_s;
    int t = threadIdx.x, lane = t & 31, w = t >> 5;
    if (t == 0) carry_s = 0;
    __syncthreads();
    for (int base = 0; base < N_NODES; base += 1024) {
        int i = base + t;
        int v = (i < N_NODES) ? g_degi[i] : 0;
        int x = v;
        #pragma unroll
        for (int off = 1; off < 32; off <<= 1) {
            int y = __shfl_up_sync(0xffffffffu, x, off);
            if (lane >= off) x += y;
        }
        if (lane == 31) wsum[w] = x;
        __syncthreads();
        if (w == 0) {
            int s = wsum[lane];
            int xs = s;
            #pragma unroll
            for (int off = 1; off < 32; off <<= 1) {
                int y = __shfl_up_sync(0xffffffffu, xs, off);
                if (lane >= off) xs += y;
            }
            wsum[lane] = xs - s;  // exclusive warp offsets
        }
        __syncthreads();
        int carry = carry_s;
        int excl = carry + wsum[w] + (x - v);
        if (i < N_NODES) { g_rowptr[i] = excl; g_cursor[i] = excl; }
        __syncthreads();
        if (t == 1023) carry_s = excl + v;
        __syncthreads();
    }
    if (t == 0) g_rowptr[N_NODES] = carry_s;
}

__global__ void k_fill_csr(const int* __restrict__ src, const int* __restrict__ dst,
                           const float* __restrict__ ew) {
    int e = blockIdx.x * blockDim.x + threadIdx.x;
    if (e < N_EDGES) {
        int d = dst[e];
        int p = atomicAdd(&g_cursor[d], 1);
        g_esrc[p] = src[e];
        g_eww[p]  = ew[e];
    }
}

// C[N,128] = (A (*) scale) @ W (+ bias). W row-major [128,128].
#define GBM 64
#define GBK 32
__global__ void __launch_bounds__(256) k_gemm128(
    const float* __restrict__ A, const float* __restrict__ scale,
    const float* __restrict__ W, const float* __restrict__ bias,
    float* __restrict__ C) {
    __shared__ float As[GBM][GBK + 4];   // stride 36, float4-aligned
    __shared__ float Ws[GBK][DIM];
    const int tid  = threadIdx.x;
    const int row0 = blockIdx.x * GBM;
    const int lrow = tid >> 2;           // 0..63
    const int lq   = tid & 3;            // quad
    const int grow = row0 + lrow;
    const float s  = (grow < N_NODES) ? (scale ? scale[grow] : 1.0f) : 0.0f;
    const int tcol = tid & 31;           // 0..31
    const int trow = tid >> 5;           // 0..7
    float acc[8][4];
    #pragma unroll
    for (int m = 0; m < 8; m++)
        #pragma unroll
        for (int n = 0; n < 4; n++) acc[m][n] = 0.0f;

    for (int k0 = 0; k0 < DIM; k0 += GBK) {
        // A tile: 64 x 32, scaled
        if (grow < N_NODES) {
            float4 v0 = *(const float4*)&A[grow * DIM + k0 + lq * 4];
            float4 v1 = *(const float4*)&A[grow * DIM + k0 + (lq + 4) * 4];
            v0.x *= s; v0.y *= s; v0.z *= s; v0.w *= s;
            v1.x *= s; v1.y *= s; v1.z *= s; v1.w *= s;
            *(float4*)&As[lrow][lq * 4]       = v0;
            *(float4*)&As[lrow][(lq + 4) * 4] = v1;
        } else {
            float4 z = make_float4(0.f, 0.f, 0.f, 0.f);
            *(float4*)&As[lrow][lq * 4]       = z;
            *(float4*)&As[lrow][(lq + 4) * 4] = z;
        }
        // W tile: 32 x 128
        #pragma unroll
        for (int i = 0; i < 4; i++) {
            int u = tid + 256 * i;          // 0..1023 float4 units
            int wr = u >> 5, wc = (u & 31) * 4;
            *(float4*)&Ws[wr][wc] = *(const float4*)&W[(k0 + wr) * DIM + wc];
        }
        __syncthreads();
        #pragma unroll
        for (int k = 0; k < GBK; k++) {
            float4 b = *(const float4*)&Ws[k][tcol * 4];
            #pragma unroll
            for (int m = 0; m < 8; m++) {
                float a = As[trow * 8 + m][k];
                acc[m][0] += a * b.x;
                acc[m][1] += a * b.y;
                acc[m][2] += a * b.z;
                acc[m][3] += a * b.w;
            }
        }
        __syncthreads();
    }
    float4 bb = make_float4(0.f, 0.f, 0.f, 0.f);
    if (bias) bb = *(const float4*)&bias[tcol * 4];
    #pragma unroll
    for (int m = 0; m < 8; m++) {
        int gr = row0 + trow * 8 + m;
        if (gr < N_NODES) {
            float4 o;
            o.x = acc[m][0] + bb.x; o.y = acc[m][1] + bb.y;
            o.z = acc[m][2] + bb.z; o.w = acc[m][3] + bb.w;
            *(float4*)&C[gr * DIM + tcol * 4] = o;
        }
    }
}

// one warp per destination row: acc = sum_e w_e * h[src_e]; out = f(acc*isi + b [+res])
__global__ void __launch_bounds__(256) k_spmm(
    const float* __restrict__ h, const float* __restrict__ bias,
    const float* __restrict__ res, float* __restrict__ out, int do_relu) {
    int warp = (blockIdx.x * blockDim.x + threadIdx.x) >> 5;
    int lane = threadIdx.x & 31;
    if (warp >= N_NODES) return;
    int beg = g_rowptr[warp], end = g_rowptr[warp + 1];
    float4 acc = make_float4(0.f, 0.f, 0.f, 0.f);
    int e = beg;
    for (; e + 1 < end; e += 2) {
        int   s0 = g_esrc[e],   s1 = g_esrc[e + 1];
        float w0 = g_eww[e],    w1 = g_eww[e + 1];
        float4 v0 = *(const float4*)&h[s0 * DIM + lane * 4];
        float4 v1 = *(const float4*)&h[s1 * DIM + lane * 4];
        acc.x += w0 * v0.x + w1 * v1.x;
        acc.y += w0 * v0.y + w1 * v1.y;
        acc.z += w0 * v0.z + w1 * v1.z;
        acc.w += w0 * v0.w + w1 * v1.w;
    }
    if (e < end) {
        int s0 = g_esrc[e]; float w0 = g_eww[e];
        float4 v0 = *(const float4*)&h[s0 * DIM + lane * 4];
        acc.x += w0 * v0.x; acc.y += w0 * v0.y;
        acc.z += w0 * v0.z; acc.w += w0 * v0.w;
    }
    float si = g_isi[warp];
    float4 b = *(const float4*)&bias[lane * 4];
    float4 o;
    o.x = acc.x * si + b.x; o.y = acc.y * si + b.y;
    o.z = acc.z * si + b.z; o.w = acc.w * si + b.w;
    if (res) {
        float4 r = *(const float4*)&res[warp * DIM + lane * 4];
        o.x += r.x; o.y += r.y; o.z += r.z; o.w += r.w;
    }
    if (do_relu) {
        o.x = fmaxf(o.x, 0.f); o.y = fmaxf(o.y, 0.f);
        o.z = fmaxf(o.z, 0.f); o.w = fmaxf(o.w, 0.f);
    }
    *(float4*)&out[warp * DIM + lane * 4] = o;
}

// out[N,16] = z[N,128] @ Wo[128,16] + bo
__global__ void __launch_bounds__(256) k_out(
    const float* __restrict__ z, const float* __restrict__ Wo,
    const float* __restrict__ bo, float* __restrict__ out) {
    __shared__ float sz[64][132];
    __shared__ float sw[DIM][NCLS];
    int r0 = blockIdx.x * 64;
    for (int i = threadIdx.x; i < DIM * NCLS; i += 256)
        sw[i >> 4][i & 15] = Wo[i];
    for (int i = threadIdx.x; i < 2048; i += 256) {   // 64 rows x 32 float4
        int row = i >> 5, c4 = (i & 31) * 4;
        int gr = r0 + row;
        float4 v = (gr < N_NODES) ? *(const float4*)&z[gr * DIM + c4]
                                  : make_float4(0.f, 0.f, 0.f, 0.f);
        *(float4*)&sz[row][c4] = v;
    }
    __syncthreads();
    int row = threadIdx.x >> 2;
    int cg  = (threadIdx.x & 3) * 4;
    float a0 = 0.f, a1 = 0.f, a2 = 0.f, a3 = 0.f;
    #pragma unroll 8
    for (int k = 0; k < DIM; k++) {
        float zv = sz[row][k];
        a0 += zv * sw[k][cg];     a1 += zv * sw[k][cg + 1];
        a2 += zv * sw[k][cg + 2]; a3 += zv * sw[k][cg + 3];
    }
    int gr = r0 + row;
    if (gr < N_NODES) {
        out[gr * NCLS + cg]     = a0 + bo[cg];
        out[gr * NCLS + cg + 1] = a1 + bo[cg + 1];
        out[gr * NCLS + cg + 2] = a2 + bo[cg + 2];
        out[gr * NCLS + cg + 3] = a3 + bo[cg + 3];
    }
}

// ---------------- launch ----------------
extern "C" void kernel_launch(void* const* d_in, const int* in_sizes, int n_in,
                              void* d_out, int out_size) {
    const int*   src = (const int*)d_in[0];
    const int*   dst = (const int*)d_in[1];
    const float* xin = (const float*)d_in[2];
    const float* ew  = (const float*)d_in[3];
    const float* W1 = (const float*)d_in[4];  const float* b1 = (const float*)d_in[5];
    const float* W2 = (const float*)d_in[6];  const float* b2 = (const float*)d_in[7];
    const float* W3 = (const float*)d_in[8];  const float* b3 = (const float*)d_in[9];
    const float* W4 = (const float*)d_in[10]; const float* b4 = (const float*)d_in[11];
    const float* Wr = (const float*)d_in[12]; const float* br = (const float*)d_in[13];
    const float* Wo = (const float*)d_in[14]; const float* bo = (const float*)d_in[15];
    float* out = (float*)d_out;

    float *p_h, *p_x, *p_res, *p_iso;
    cudaGetSymbolAddress((void**)&p_h,   g_h);
    cudaGetSymbolAddress((void**)&p_x,   g_x);
    cudaGetSymbolAddress((void**)&p_res, g_res);
    cudaGetSymbolAddress((void**)&p_iso, g_iso);

    const int TB = 256;
    int nB_nodes = (N_NODES + TB - 1) / TB;       // 196
    int nB_edges = (N_EDGES + TB - 1) / TB;       // 3125
    int nB_gemm  = (N_NODES + GBM - 1) / GBM;     // 782
    int nB_spmm  = (N_NODES + (TB / 32) - 1) / (TB / 32);  // 6250

    // graph preprocessing (identical for all 4 layers)
    k_zero_deg<<<nB_nodes, TB>>>();
    k_degrees<<<nB_edges, TB>>>(src, dst);
    k_invsqrt<<<nB_nodes, TB>>>();
    k_scan<<<1, 1024>>>();
    k_fill_csr<<<nB_edges, TB>>>(src, dst, ew);

    // residual branch
    k_gemm128<<<nB_gemm, TB>>>(xin, nullptr, Wr, br, p_res);

    // layer 1
    k_gemm128<<<nB_gemm, TB>>>(xin, p_iso, W1, nullptr, p_h);
    k_spmm<<<nB_spmm, TB>>>(p_h, b1, nullptr, p_x, 1);
    // layer 2
    k_gemm128<<<nB_gemm, TB>>>(p_x, p_iso, W2, nullptr, p_h);
    k_spmm<<<nB_spmm, TB>>>(p_h, b2, nullptr, p_x, 1);
    // layer 3
    k_gemm128<<<nB_gemm, TB>>>(p_x, p_iso, W3, nullptr, p_h);
    k_spmm<<<nB_spmm, TB>>>(p_h, b3, nullptr, p_x, 1);
    // layer 4 + residual + relu
    k_gemm128<<<nB_gemm, TB>>>(p_x, p_iso, W4, nullptr, p_h);
    k_spmm<<<nB_spmm, TB>>>(p_h, b4, p_res, p_x, 1);

    // output head
    k_out<<<nB_gemm, TB>>>(p_x, Wo, bo, out);
}